// round 1
// baseline (speedup 1.0000x reference)
#include <cuda_runtime.h>
#include <cuda_bf16.h>

// 2x FIR upsample (upfirdn2d), separable [1,3,3,1] tap, depthwise, fp32.
// Input  (B*C, 128, 128), Output (B*C, 256, 256).
//
// Math (derived from lhs_dilation=2, pad=2, k = outer([1,3,3,1])/16):
//   out[2y  ] = (1*x[y-1] + 3*x[y  ]) / 4   (vertical), same horizontally
//   out[2y+1] = (3*x[y  ] + 1*x[y+1]) / 4
// Out-of-range input rows/cols contribute zero.

#define H_IN  128
#define W_IN  128
#define W_OUT 256

__global__ __launch_bounds__(256) void upfir2x_kernel(
    const float* __restrict__ in, float* __restrict__ out)
{
    const int bc = blockIdx.z;                         // batch*channel plane
    const int oy = blockIdx.y * blockDim.y + threadIdx.y;  // 0..255 output row
    const int tx = threadIdx.x;                        // 0..63, covers 4 out px each

    const float* src = in + (size_t)bc * (H_IN * W_IN);

    const int y = oy >> 1;
    const int r = oy & 1;
    // vertical taps
    int yA, yB; float wA, wB;
    if (r == 0) { yA = y - 1; yB = y;     wA = 1.0f; wB = 3.0f; }
    else        { yA = y;     yB = y + 1; wA = 3.0f; wB = 1.0f; }

    const bool vA = (yA >= 0) && (yA < H_IN);
    const bool vB = (yB >= 0) && (yB < H_IN);

    const int xb = tx * 2;   // input column base; need cols xb-1 .. xb+2

    // Row A loads (zero-fill OOB). xb is even -> &row[xb] is 8B aligned: float2.
    float a0 = 0.f, a1 = 0.f, a2 = 0.f, a3 = 0.f;
    if (vA) {
        const float* rA = src + yA * W_IN;
        if (xb > 0) a0 = __ldg(rA + xb - 1);
        float2 m = *reinterpret_cast<const float2*>(rA + xb);
        a1 = m.x; a2 = m.y;
        if (xb + 2 < W_IN) a3 = __ldg(rA + xb + 2);
    }
    float b0 = 0.f, b1 = 0.f, b2 = 0.f, b3 = 0.f;
    if (vB) {
        const float* rB = src + yB * W_IN;
        if (xb > 0) b0 = __ldg(rB + xb - 1);
        float2 m = *reinterpret_cast<const float2*>(rB + xb);
        b1 = m.x; b2 = m.y;
        if (xb + 2 < W_IN) b3 = __ldg(rB + xb + 2);
    }

    // Horizontal 2-tap (unnormalized):
    //   even ox=2x : 1*col[x-1] + 3*col[x]
    //   odd  ox    : 3*col[x]   + 1*col[x+1]
    float hA0 = fmaf(3.f, a1, a0);
    float hA1 = fmaf(3.f, a1, a2);
    float hA2 = fmaf(3.f, a2, a1);
    float hA3 = fmaf(3.f, a2, a3);

    float hB0 = fmaf(3.f, b1, b0);
    float hB1 = fmaf(3.f, b1, b2);
    float hB2 = fmaf(3.f, b2, b1);
    float hB3 = fmaf(3.f, b2, b3);

    const float s = 1.0f / 16.0f;
    float4 o;
    o.x = (wA * hA0 + wB * hB0) * s;
    o.y = (wA * hA1 + wB * hB1) * s;
    o.z = (wA * hA2 + wB * hB2) * s;
    o.w = (wA * hA3 + wB * hB3) * s;

    float* dst = out + (size_t)bc * (W_OUT * W_OUT) + (size_t)oy * W_OUT + tx * 4;
    *reinterpret_cast<float4*>(dst) = o;
}

extern "C" void kernel_launch(void* const* d_in, const int* in_sizes, int n_in,
                              void* d_out, int out_size) {
    const float* x = (const float*)d_in[0];
    float* out = (float*)d_out;

    const int planes = in_sizes[0] / (H_IN * W_IN);   // B*C = 1024

    dim3 block(64, 4, 1);           // 64 threads cover 256-wide row as float4
    dim3 grid(1, W_OUT / 4, planes);
    upfir2x_kernel<<<grid, block>>>(x, out);
}